// round 15
// baseline (speedup 1.0000x reference)
#include <cuda_runtime.h>
#include <cuda_fp16.h>
#include <cstdint>
#include <math.h>

// ---------------------------------------------------------------------------
// Problem constants
// ---------------------------------------------------------------------------
#define H     128
#define MSG   256
#define TM    32          // rows per tile
#define NSTRIDE 74        // persistent tile stride (296 CTAs, all resident)
#define NTHREADS 256
#define WSTB  784         // smem row stride bytes (384 halves = 768B + 16 pad)

#define SLAB_BYTE (96 * WSTB)              // 75264 : 3 gates x 32 cols (quarter)
#define A_BYTE    SLAB_BYTE
#define SMEM_BYTES (SLAB_BYTE + TM * WSTB) // 100352 -> 2 CTAs/SM

// fp16 weight scratch + updated-row flags
__device__ half          g_Wih_h[384 * MSG];
__device__ half          g_Whh_h[384 * H];
__device__ unsigned char g_flag[1 << 20];

__device__ __forceinline__ void ldsm_x4(uint32_t* r, uint32_t addr) {
    asm volatile("ldmatrix.sync.aligned.m8n8.x4.shared.b16 {%0,%1,%2,%3}, [%4];"
                 : "=r"(r[0]), "=r"(r[1]), "=r"(r[2]), "=r"(r[3]) : "r"(addr));
}
__device__ __forceinline__ void mma_f16(float* d, const uint32_t* a,
                                        uint32_t b0, uint32_t b1) {
    asm("mma.sync.aligned.m16n8k16.row.col.f32.f16.f16.f32 "
        "{%0,%1,%2,%3}, {%4,%5,%6,%7}, {%8,%9}, {%0,%1,%2,%3};"
        : "+f"(d[0]), "+f"(d[1]), "+f"(d[2]), "+f"(d[3])
        : "r"(a[0]), "r"(a[1]), "r"(a[2]), "r"(a[3]), "r"(b0), "r"(b1));
}
__device__ __forceinline__ uint32_t pack_h2(float x, float y) {
    half2 h = __float22half2_rn(make_float2(x, y));
    return *(uint32_t*)&h;
}
__device__ __forceinline__ void cp16(uint32_t smem_addr, const void* gptr) {
    asm volatile("cp.async.ca.shared.global [%0], [%1], 16;"
                 :: "r"(smem_addr), "l"(gptr) : "memory");
}
#define CP_COMMIT() asm volatile("cp.async.commit_group;" ::: "memory")
#define CP_WAIT0()  asm volatile("cp.async.wait_group 0;" ::: "memory")

// ---------------------------------------------------------------------------
// Prep kernels (split so the two stream branches can start immediately)
// ---------------------------------------------------------------------------
__global__ void prep_w_kernel(const float* __restrict__ W_ih,
                              const float* __restrict__ W_hh) {
    int i = blockIdx.x * blockDim.x + threadIdx.x;
    int stride = gridDim.x * blockDim.x;
    for (int j = i; j < 384 * MSG + 384 * H; j += stride) {
        if (j < 384 * MSG) g_Wih_h[j] = __float2half_rn(W_ih[j]);
        else               g_Whh_h[j - 384 * MSG] = __float2half_rn(W_hh[j - 384 * MSG]);
    }
}
__global__ void prep_f_kernel(int n16) {       // zero flags as uint4
    int i = blockIdx.x * blockDim.x + threadIdx.x;
    if (i < n16) ((uint4*)g_flag)[i] = make_uint4(0, 0, 0, 0);
}
__global__ void flag_kernel(const int* __restrict__ node_ids, int B) {
    int i = blockIdx.x * blockDim.x + threadIdx.x;
    if (i < B) g_flag[node_ids[i]] = 1;
}

// ---------------------------------------------------------------------------
// Selective clone: finite-work blocks (32 rows each, 128 threads).
// Co-schedules into SM slots left free by the GRU kernel.
// ---------------------------------------------------------------------------
__global__ __launch_bounds__(128)
void clone_sel_kernel(const float* __restrict__ memory,
                      const float* __restrict__ last_update,
                      float* __restrict__ out_mem,
                      float* __restrict__ out_lu,
                      int n_nodes) {
    const long row0 = (long)blockIdx.x * 32;
    const int  lane = threadIdx.x & 31;
    const int  w    = threadIdx.x >> 5;
    #pragma unroll
    for (int i = 0; i < 8; i++) {
        long row = row0 + w + i * 4;
        if (row < n_nodes && !g_flag[row])
            ((float4*)(out_mem + row * H))[lane] =
                ((const float4*)(memory + row * H))[lane];
    }
    if (threadIdx.x < 32) {
        long row = row0 + threadIdx.x;
        if (row < n_nodes && !g_flag[row]) out_lu[row] = last_update[row];
    }
}

// ---------------------------------------------------------------------------
// Weight-resident persistent GRU (round-12 mainloop; register prefetch
// removed -> ~100 regs -> clone blocks can co-schedule).
// grid = 4*NSTRIDE = 296 (all resident); ch = bid&3 -> gate-column quarter.
// ---------------------------------------------------------------------------
__global__ __launch_bounds__(NTHREADS, 2)
void gru_persist_kernel(const float* __restrict__ memory,
                        const int*   __restrict__ node_ids,
                        const float* __restrict__ X,
                        const float* __restrict__ ts,
                        const float* __restrict__ b_ih,
                        const float* __restrict__ b_hh,
                        float* __restrict__ out_mem,
                        float* __restrict__ out_lu,
                        int B, int ntiles)
{
    extern __shared__ char smc[];
    const uint32_t sh_base = (uint32_t)__cvta_generic_to_shared(smc);

    const int tid  = threadIdx.x;
    const int lane = tid & 31;
    const int wid  = tid >> 5;
    const int wr   = wid >> 2;
    const int wn   = wid & 3;
    const int gid  = lane >> 2;
    const int tig  = lane & 3;
    const int ch   = blockIdx.x & 3;
    const int tstart = blockIdx.x >> 2;

    const int colb = ch * 32 + wn * 8 + tig * 2;
    const float brz0 = b_ih[colb]           + b_hh[colb];
    const float brz1 = b_ih[colb + 1]       + b_hh[colb + 1];
    const float bzz0 = b_ih[128 + colb]     + b_hh[128 + colb];
    const float bzz1 = b_ih[128 + colb + 1] + b_hh[128 + colb + 1];
    const float bin0 = b_ih[256 + colb],     bin1 = b_ih[256 + colb + 1];
    const float bhn0 = b_hh[256 + colb],     bhn1 = b_hh[256 + colb + 1];

    // ---- weight slab: 96 rows x 784B, loaded once ----
    #pragma unroll
    for (int i = 0; i < 18; i++) {
        int idx = tid + i * NTHREADS;
        int n = idx / 48, u = idx - n * 48;
        int wrow = ((n >> 5) << 7) + (ch << 5) + (n & 31);
        if (u < 32) cp16(sh_base + (uint32_t)(n * WSTB + u * 16),
                         g_Wih_h + (long)wrow * MSG + u * 8);
        else        cp16(sh_base + (uint32_t)(n * WSTB + 512 + (u - 32) * 16),
                         g_Whh_h + (long)wrow * H + (u - 32) * 8);
    }
    CP_COMMIT();

    // ---- A fill (direct, transient registers only) ----
    const int a_r = tid >> 3, u0 = tid & 7;
    auto fill_A = [&](int tile) {
        long grow = (long)tile * TM + a_r; if (grow >= B) grow = B - 1;
        const float4* xs = (const float4*)(X + grow * MSG);
        char* dst = smc + A_BYTE + a_r * WSTB;
        #pragma unroll
        for (int j = 0; j < 4; j++) {
            int u = u0 + j * 8;
            float4 v0 = xs[u * 2], v1 = xs[u * 2 + 1];
            *(uint4*)(dst + u * 16) = make_uint4(pack_h2(v0.x, v0.y), pack_h2(v0.z, v0.w),
                                                 pack_h2(v1.x, v1.y), pack_h2(v1.z, v1.w));
        }
        int node = node_ids[grow];
        const float4* ms = (const float4*)(memory + (long)node * H);
        #pragma unroll
        for (int j = 0; j < 2; j++) {
            int u = u0 + j * 8;
            float4 v0 = ms[u * 2], v1 = ms[u * 2 + 1];
            *(uint4*)(dst + 512 + u * 16) = make_uint4(pack_h2(v0.x, v0.y), pack_h2(v0.z, v0.w),
                                                       pack_h2(v1.x, v1.y), pack_h2(v1.z, v1.w));
        }
    };

    fill_A(tstart);
    CP_WAIT0();
    __syncthreads();

    const int lane8 = lane & 7, laneA = lane & 15;
    const uint32_t aB0 = sh_base + (uint32_t)A_BYTE
                       + (uint32_t)laneA * WSTB + (uint32_t)(lane >> 4) * 16;
    const uint32_t aB1 = aB0 + 16u * WSTB;
    const uint32_t bOff0 = sh_base + (uint32_t)((wn * 8 + lane8) * WSTB)
                         + (uint32_t)(lane >> 3) * 16;
    const uint32_t bOff1 = bOff0 + 32u * WSTB;
    const uint32_t bOff2 = bOff0 + 64u * WSTB;

    for (int tile = tstart; tile < ntiles; tile += NSTRIDE) {
        const int  next     = tile + NSTRIDE;
        const bool has_next = next < ntiles;

        // epilogue h prefetch (small: 2 nodes + 2 float2)
        int    hnode[2];
        float2 hv[2];
        #pragma unroll
        for (int sr = 0; sr < 2; sr++) {
            long grow = (long)tile * TM + wr * 16 + gid + sr * 8;
            if (grow >= B) grow = B - 1;
            int node = node_ids[grow];
            hnode[sr] = node;
            hv[sr] = *(const float2*)(memory + (long)node * H + colb);
        }

        float acc[4][4];   // 0=r 1=z 2=i_n 3=h_n
        #pragma unroll
        for (int g = 0; g < 4; g++)
            #pragma unroll
            for (int j = 0; j < 4; j++) acc[g][j] = 0.f;

        const uint32_t aB = (wr == 0) ? aB0 : aB1;
        #pragma unroll
        for (int c = 0; c < 12; c++) {
            const uint32_t ko = (uint32_t)c * 64u;
            uint32_t a[2][4], bb[3][4];
            ldsm_x4(a[0], aB + ko);
            ldsm_x4(a[1], aB + ko + 32);
            ldsm_x4(bb[0], bOff0 + ko);
            ldsm_x4(bb[1], bOff1 + ko);
            ldsm_x4(bb[2], bOff2 + ko);
            const int ng = (c < 8) ? 2 : 3;
            mma_f16(acc[0],  a[0], bb[0][0], bb[0][1]);
            mma_f16(acc[0],  a[1], bb[0][2], bb[0][3]);
            mma_f16(acc[1],  a[0], bb[1][0], bb[1][1]);
            mma_f16(acc[1],  a[1], bb[1][2], bb[1][3]);
            mma_f16(acc[ng], a[0], bb[2][0], bb[2][1]);
            mma_f16(acc[ng], a[1], bb[2][2], bb[2][3]);
        }

        // epilogue: gates + scatter
        #pragma unroll
        for (int sr = 0; sr < 2; sr++) {
            const long grow = (long)tile * TM + wr * 16 + gid + sr * 8;
            if (grow < B) {
                const int f = sr * 2;
                float rg0 = 1.0f / (1.0f + __expf(-(acc[0][f]     + brz0)));
                float rg1 = 1.0f / (1.0f + __expf(-(acc[0][f + 1] + brz1)));
                float zg0 = 1.0f / (1.0f + __expf(-(acc[1][f]     + bzz0)));
                float zg1 = 1.0f / (1.0f + __expf(-(acc[1][f + 1] + bzz1)));
                float ng0 = tanhf(acc[2][f]     + bin0 + rg0 * (acc[3][f]     + bhn0));
                float ng1 = tanhf(acc[2][f + 1] + bin1 + rg1 * (acc[3][f + 1] + bhn1));
                *(float2*)(out_mem + (long)hnode[sr] * H + colb) =
                    make_float2((1.0f - zg0) * ng0 + zg0 * hv[sr].x,
                                (1.0f - zg1) * ng1 + zg1 * hv[sr].y);
            }
        }
        if (ch == 0 && tid < TM) {
            long grow = (long)tile * TM + tid;
            if (grow < B) out_lu[node_ids[grow]] = ts[grow];
        }

        // refill A for next tile (transient regs; other CTA + clone hide it)
        __syncthreads();
        if (has_next) {
            fill_A(next);
            __syncthreads();
        }
    }
}

// ---------------------------------------------------------------------------
// Launch. Forked from the start:
//   stream0: [e0] -> prep_w -> gru ---------------- [wait e2]
//   s2:      [wait e0] -> prep_f -> flag -> clone -> [e2]
// Writes disjoint via g_flag; clone co-schedules into free SM slots.
// ---------------------------------------------------------------------------
extern "C" void kernel_launch(void* const* d_in, const int* in_sizes, int n_in,
                              void* d_out, int out_size) {
    const float* memory      = (const float*)d_in[0];
    const float* last_update = (const float*)d_in[1];
    const int*   node_ids    = (const int*)  d_in[2];
    const float* X           = (const float*)d_in[3];
    const float* ts          = (const float*)d_in[4];
    const float* W_ih        = (const float*)d_in[5];
    const float* W_hh        = (const float*)d_in[6];
    const float* b_ih        = (const float*)d_in[7];
    const float* b_hh        = (const float*)d_in[8];

    const int n_nodes = in_sizes[1];
    const int B       = in_sizes[2];

    float* out_mem = (float*)d_out;
    float* out_lu  = out_mem + (long)n_nodes * H;

    static cudaStream_t s2 = nullptr;
    static cudaEvent_t  e0 = nullptr, e2 = nullptr;
    if (s2 == nullptr) {
        cudaStreamCreateWithFlags(&s2, cudaStreamNonBlocking);
        cudaEventCreateWithFlags(&e0, cudaEventDisableTiming);
        cudaEventCreateWithFlags(&e2, cudaEventDisableTiming);
        cudaFuncSetAttribute(gru_persist_kernel,
                             cudaFuncAttributeMaxDynamicSharedMemorySize, SMEM_BYTES);
    }

    cudaEventRecord(e0, 0);
    cudaStreamWaitEvent(s2, e0, 0);

    // branch A (default stream): weights -> GRU
    prep_w_kernel<<<288, 512>>>(W_ih, W_hh);
    {
        int ntiles = (B + TM - 1) / TM;
        gru_persist_kernel<<<4 * NSTRIDE, NTHREADS, SMEM_BYTES>>>(
            memory, node_ids, X, ts, b_ih, b_hh, out_mem, out_lu, B, ntiles);
    }

    // branch B (s2): flags -> selective clone (concurrent with GRU)
    {
        int n16 = (n_nodes + 15) / 16;
        prep_f_kernel<<<(n16 + 511) / 512, 512, 0, s2>>>(n16);
        flag_kernel<<<(B + 511) / 512, 512, 0, s2>>>(node_ids, B);
        int cblocks = (n_nodes + 31) / 32;
        clone_sel_kernel<<<cblocks, 128, 0, s2>>>(memory, last_update,
                                                  out_mem, out_lu, n_nodes);
    }
    cudaEventRecord(e2, s2);
    cudaStreamWaitEvent(0, e2, 0);
}